// round 11
// baseline (speedup 1.0000x reference)
#include <cuda_runtime.h>
#include <cuda_fp16.h>
#include <cstdint>

#define N_NODES 50000
#define N_EDGES 800000
#define ET (N_EDGES + N_NODES)   // edges + self loops = 850000
#define IN_CH 128
#define H1 8
#define C1 64
#define F1 (H1 * C1)             // 512
#define NEG_SLOPE 0.2f

// ---------------- scratch (static device globals; no allocation) ------------
__device__ __half g_h1h[N_NODES * F1];    // x @ W1 in fp16   (51.2 MB, L2-resident)
__device__ float g_as1[N_NODES * H1];
__device__ float g_ad1[N_NODES * H1];
__device__ float g_h2[N_NODES * 2];
__device__ float g_as2[N_NODES];
__device__ float g_ad2[N_NODES];
__device__ int   g_deg[N_NODES];
__device__ int   g_off[N_NODES + 1];
__device__ int   g_cur[N_NODES];
__device__ int   g_csr_src[ET];
__device__ int   g_bar1, g_bar2;          // grid-barrier counters (monotonic)

__device__ __half g_ah[N_NODES * IN_CH];   // fp16(x)    [m][k]
__device__ __half g_bh[F1 * IN_CH];        // fp16(W1^T) [n][k]

// ---------------- PTX helpers ------------------------------------------------
__device__ __forceinline__ uint32_t smem_u32(const void* p) {
    uint32_t a;
    asm("{ .reg .u64 t; cvta.to.shared.u64 t, %1; cvt.u32.u64 %0, t; }"
        : "=r"(a) : "l"(p));
    return a;
}

__device__ __forceinline__ void ldm_x4(uint32_t* r, uint32_t addr) {
    asm volatile("ldmatrix.sync.aligned.m8n8.x4.shared.b16 {%0,%1,%2,%3}, [%4];"
                 : "=r"(r[0]), "=r"(r[1]), "=r"(r[2]), "=r"(r[3]) : "r"(addr));
}

__device__ __forceinline__ void mma_fp16(float* d, const uint32_t* a,
                                         const uint32_t* b) {
    asm volatile("mma.sync.aligned.m16n8k16.row.col.f32.f16.f16.f32 "
                 "{%0,%1,%2,%3}, {%4,%5,%6,%7}, {%8,%9}, {%0,%1,%2,%3};"
                 : "+f"(d[0]), "+f"(d[1]), "+f"(d[2]), "+f"(d[3])
                 : "r"(a[0]), "r"(a[1]), "r"(a[2]), "r"(a[3]),
                   "r"(b[0]), "r"(b[1]));
}

__device__ __forceinline__ void cp16(uint32_t dst, const void* src,
                                     uint32_t src_bytes) {
    asm volatile("cp.async.cg.shared.global [%0], [%1], 16, %2;"
                 :: "r"(dst), "l"(src), "r"(src_bytes));
}

__device__ __forceinline__ uint4 ldcg128(const uint4* p) {
    uint4 v;
    asm volatile("ld.global.cg.v4.u32 {%0,%1,%2,%3}, [%4];"
                 : "=r"(v.x), "=r"(v.y), "=r"(v.z), "=r"(v.w) : "l"(p));
    return v;
}

// ---------------- fused CSR build (single grid-resident kernel) --------------
// grid = 148 blocks x 1024 threads (1 block/SM guaranteed resident).
// Software grid barrier: monotonic counter; replays serialize so
// (base / gridDim) is the replay index and targets never collide.
__device__ __forceinline__ void grid_barrier(int* ctr, int grid) {
    __syncthreads();
    if (threadIdx.x == 0) {
        __threadfence();
        int base = atomicAdd(ctr, 1);
        int target = (base / grid + 1) * grid;
        while (*(volatile int*)ctr < target) __nanosleep(64);
        __threadfence();
    }
    __syncthreads();
}

__global__ void __launch_bounds__(1024, 1) k_csr(const int* __restrict__ ei) {
    int gstride = gridDim.x * blockDim.x;
    int gtid = blockIdx.x * blockDim.x + threadIdx.x;

    // phase A: degree histogram
    for (int e = gtid; e < N_EDGES; e += gstride)
        atomicAdd(&g_deg[ei[N_EDGES + e]], 1);

    grid_barrier(&g_bar1, gridDim.x);

    // phase B: exclusive scan (block 0 only; adds self-loop, zeroes g_deg)
    if (blockIdx.x == 0) {
        __shared__ int wsum[2][32];
        int t = threadIdx.x, lane = t & 31, w = t >> 5;
        int carry = 0;
        int p = 0;
        for (int base = 0; base < N_NODES; base += 4096, p ^= 1) {
            int i = base + t * 4;
            int c0 = 0, c1 = 0, c2 = 0, c3 = 0;
            if (i + 3 < N_NODES) {
                int4 v = *(int4*)&g_deg[i];
                *(int4*)&g_deg[i] = make_int4(0, 0, 0, 0);
                c0 = v.x + 1; c1 = v.y + 1; c2 = v.z + 1; c3 = v.w + 1;
            } else if (i < N_NODES) {
                int cc[4] = {0, 0, 0, 0};
                for (int q = 0; q < 4; q++)
                    if (i + q < N_NODES) { cc[q] = g_deg[i + q] + 1; g_deg[i + q] = 0; }
                c0 = cc[0]; c1 = cc[1]; c2 = cc[2]; c3 = cc[3];
            }
            int tsum = c0 + c1 + c2 + c3;
            int s = tsum;
            #pragma unroll
            for (int o = 1; o < 32; o <<= 1) {
                int u = __shfl_up_sync(0xffffffffu, s, o);
                if (lane >= o) s += u;
            }
            if (lane == 31) wsum[p][w] = s;
            __syncthreads();
            if (w == 0) {
                int ws = wsum[p][lane];
                #pragma unroll
                for (int o = 1; o < 32; o <<= 1) {
                    int u = __shfl_up_sync(0xffffffffu, ws, o);
                    if (lane >= o) ws += u;
                }
                wsum[p][lane] = ws;
            }
            __syncthreads();
            int excl = carry + (w ? wsum[p][w - 1] : 0) + s - tsum;
            int o0 = excl, o1 = o0 + c0, o2 = o1 + c1, o3 = o2 + c2;
            if (i + 3 < N_NODES) {
                *(int4*)&g_off[i] = make_int4(o0, o1, o2, o3);
                *(int4*)&g_cur[i] = make_int4(o0, o1, o2, o3);
            } else {
                int oo[4] = {o0, o1, o2, o3};
                for (int q = 0; q < 4; q++)
                    if (i + q < N_NODES) { g_off[i + q] = oo[q]; g_cur[i + q] = oo[q]; }
            }
            carry += wsum[p][31];
        }
        if (t == 0) g_off[N_NODES] = carry;   // = ET
    }

    grid_barrier(&g_bar2, gridDim.x);

    // phase C: scatter
    for (int e = gtid; e < ET; e += gstride) {
        int src, dst;
        if (e < N_EDGES) { src = ei[e]; dst = ei[N_EDGES + e]; }
        else             { src = dst = e - N_EDGES; }
        int pos = atomicAdd(&g_cur[dst], 1);
        g_csr_src[pos] = src;
    }
}

// ---------------- operand prep (merged a + b) ---------------------------------
#define PREP_NA (N_NODES * IN_CH / 4)    // 1,600,000 float4s of x
__global__ void k_prep(const float* __restrict__ x, const float* __restrict__ W) {
    int idx = blockIdx.x * blockDim.x + threadIdx.x;
    if (idx < PREP_NA) {
        float4 v = ((const float4*)x)[idx];
        __half2 h0 = __floats2half2_rn(v.x, v.y);
        __half2 h1 = __floats2half2_rn(v.z, v.w);
        ((uint2*)g_ah)[idx] = make_uint2(*(uint32_t*)&h0, *(uint32_t*)&h1);
    } else {
        int i2 = idx - PREP_NA;
        if (i2 < F1 * IN_CH) {
            int n = i2 & (F1 - 1);
            int k = i2 >> 9;
            g_bh[n * IN_CH + k] = __float2half_rn(W[k * F1 + n]);
        }
    }
}

// ---------------- mma.sync GEMM: h1 = X @ W1  (+ fused attention scores) -----
#define AS_STRIDE 136             // halves per row (272B: 16B-aligned, 8-row conflict-free)
#define TILE_BYTES_SM (128 * AS_STRIDE * 2)      // 34816
#define GEMM_SMEM (2 * TILE_BYTES_SM + 1024)     // A + B + scs

__global__ void __launch_bounds__(256) k_gemm_mma(
        const float* __restrict__ asrc, const float* __restrict__ adst) {
    extern __shared__ char dyn[];
    uint32_t sA = smem_u32(dyn);
    uint32_t sB = sA + TILE_BYTES_SM;
    float* scs = (float*)(dyn + 2 * TILE_BYTES_SM);  // [0,128) a_src, [128,256) a_dst

    int tid = threadIdx.x;
    int lane = tid & 31, wid = tid >> 5;
    int wm = wid & 3, wn = wid >> 2;
    int bm = blockIdx.x * 128;
    int nb = blockIdx.y;                 // N block: cols [nb*128, nb*128+128)

    #pragma unroll
    for (int it = 0; it < 8; it++) {
        int idx = tid + it * 256;        // 0..2047
        int r = idx >> 4, c = idx & 15;
        int grow = bm + r;
        int ok = grow < N_NODES;
        const void* gp = g_ah + (size_t)(ok ? grow : 0) * IN_CH + c * 8;
        cp16(sA + (uint32_t)(r * AS_STRIDE + c * 8) * 2, gp, ok ? 16u : 0u);
    }
    #pragma unroll
    for (int it = 0; it < 8; it++) {
        int idx = tid + it * 256;
        int r = idx >> 4, c = idx & 15;
        const void* gp = g_bh + (size_t)(nb * 128 + r) * IN_CH + c * 8;
        cp16(sB + (uint32_t)(r * AS_STRIDE + c * 8) * 2, gp, 16u);
    }
    asm volatile("cp.async.commit_group;" ::: "memory");

    scs[tid] = (tid < 128) ? asrc[nb * 128 + tid] : adst[nb * 128 + tid - 128];

    float acc[2][8][4];
    #pragma unroll
    for (int i = 0; i < 2; i++)
        #pragma unroll
        for (int j = 0; j < 8; j++)
            #pragma unroll
            for (int q = 0; q < 4; q++) acc[i][j][q] = 0.f;

    uint32_t a_off0 = (uint32_t)((wm * 32 + (lane & 15)) * AS_STRIDE +
                                 (lane >> 4) * 8) * 2;
    uint32_t b_off0 = (uint32_t)(((lane >> 4) * 8 + (lane & 7)) * AS_STRIDE +
                                 ((lane >> 3) & 1) * 8) * 2;

    asm volatile("cp.async.wait_group 0;" ::: "memory");
    __syncthreads();

    #pragma unroll
    for (int ks = 0; ks < 8; ks++) {
        uint32_t af[2][4], bf[4][4];
        #pragma unroll
        for (int mt = 0; mt < 2; mt++)
            ldm_x4(af[mt], sA + a_off0 +
                   (uint32_t)(mt * 16 * AS_STRIDE + ks * 16) * 2);
        #pragma unroll
        for (int np = 0; np < 4; np++)
            ldm_x4(bf[np], sB + b_off0 +
                   (uint32_t)((wn * 64 + np * 16) * AS_STRIDE + ks * 16) * 2);
        #pragma unroll
        for (int mt = 0; mt < 2; mt++)
            #pragma unroll
            for (int np = 0; np < 4; np++) {
                mma_fp16(acc[mt][np * 2 + 0], af[mt], &bf[np][0]);
                mma_fp16(acc[mt][np * 2 + 1], af[mt], &bf[np][2]);
            }
    }

    // ---- epilogue: store h1 (fp16) + fused per-head attention scores --------
    int ql = lane & 3, qr = lane >> 2;
    int head = nb * 2 + wn;

    #pragma unroll
    for (int mt = 0; mt < 2; mt++) {
        int row0 = bm + wm * 32 + mt * 16 + qr;
        float sa0 = 0.f, sd0 = 0.f, sa8 = 0.f, sd8 = 0.f;
        #pragma unroll
        for (int nt = 0; nt < 8; nt++) {
            float d0 = acc[mt][nt][0], d1 = acc[mt][nt][1];
            float d2 = acc[mt][nt][2], d3 = acc[mt][nt][3];
            int cw = wn * 64 + nt * 8 + ql * 2;
            float v0 = scs[cw], v1 = scs[cw + 1];
            float u0 = scs[128 + cw], u1 = scs[128 + cw + 1];
            sa0 += d0 * v0 + d1 * v1;
            sd0 += d0 * u0 + d1 * u1;
            sa8 += d2 * v0 + d3 * v1;
            sd8 += d2 * u0 + d3 * u1;
            int col = nb * 128 + cw;
            if (row0 < N_NODES)
                *(__half2*)(g_h1h + (size_t)row0 * F1 + col) =
                    __floats2half2_rn(d0, d1);
            if (row0 + 8 < N_NODES)
                *(__half2*)(g_h1h + (size_t)(row0 + 8) * F1 + col) =
                    __floats2half2_rn(d2, d3);
        }
        #pragma unroll
        for (int o = 1; o <= 2; o <<= 1) {
            sa0 += __shfl_xor_sync(0xffffffffu, sa0, o);
            sd0 += __shfl_xor_sync(0xffffffffu, sd0, o);
            sa8 += __shfl_xor_sync(0xffffffffu, sa8, o);
            sd8 += __shfl_xor_sync(0xffffffffu, sd8, o);
        }
        if (ql == 0) {
            if (row0 < N_NODES) {
                g_as1[row0 * H1 + head] = sa0;
                g_ad1[row0 * H1 + head] = sd0;
            }
            if (row0 + 8 < N_NODES) {
                g_as1[(row0 + 8) * H1 + head] = sa8;
                g_ad1[(row0 + 8) * H1 + head] = sd8;
            }
        }
    }
}

// ---- layer-1 softmax + aggregation + bias + elu + FUSED layer-2 projection --
// 4 nodes per 256-thread block; 64-thread group per node, thread owns 8
// channels, ld.global.cg uint4 feature loads, gather unrolled x4.
__global__ void __launch_bounds__(256) k_agg1(const float* __restrict__ b1,
                                              const float* __restrict__ W2,
                                              const float* __restrict__ asrc2,
                                              const float* __restrict__ adst2) {
    __shared__ int   ssrc[4][64];
    __shared__ float sw[4][64][8];
    __shared__ float sadn[4][8];
    __shared__ float red[4][2][2];
    __shared__ int   smaxd;

    int tid = threadIdx.x;
    int g = tid >> 6;          // node group 0..3
    int t = tid & 63;          // thread in group
    int n = blockIdx.x * 4 + g;          // 50000 = 12500*4, always valid
    int ht = t >> 3;           // head owned by this thread

    int start = g_off[n];
    int deg = g_off[n + 1] - start;
    if (t < 8) sadn[g][t] = g_ad1[n * H1 + t];
    if (tid == 0) smaxd = 0;
    __syncthreads();
    if (t == 0) atomicMax(&smaxd, deg);
    __syncthreads();
    int maxdeg = smaxd;

    float acc[8] = {0.f, 0.f, 0.f, 0.f, 0.f, 0.f, 0.f, 0.f};
    float den = 0.f;
    const uint4* h8 = (const uint4*)g_h1h;   // 8 halves per uint4, row=64 uint4

    for (int c0 = 0; c0 < maxdeg; c0 += 64) {
        int clen = deg - c0;
        clen = (clen > 64) ? 64 : clen;
        if (t < clen) {
            int src = g_csr_src[start + c0 + t];
            ssrc[g][t] = src;
            float4 s01 = *(const float4*)(g_as1 + src * H1);
            float4 s45 = *(const float4*)(g_as1 + src * H1 + 4);
            float es[8] = {s01.x, s01.y, s01.z, s01.w,
                           s45.x, s45.y, s45.z, s45.w};
            float wv[8];
            #pragma unroll
            for (int h = 0; h < 8; h++) {
                float e = es[h] + sadn[g][h];
                e = (e > 0.f) ? e : NEG_SLOPE * e;
                wv[h] = __expf(e);
            }
            *(float4*)&sw[g][t][0] = make_float4(wv[0], wv[1], wv[2], wv[3]);
            *(float4*)&sw[g][t][4] = make_float4(wv[4], wv[5], wv[6], wv[7]);
        }
        __syncthreads();

        int jj = 0;
        for (; jj + 4 <= clen; jj += 4) {
            int s0 = ssrc[g][jj + 0], s1 = ssrc[g][jj + 1];
            int s2 = ssrc[g][jj + 2], s3 = ssrc[g][jj + 3];
            float w0 = sw[g][jj + 0][ht], w1 = sw[g][jj + 1][ht];
            float w2 = sw[g][jj + 2][ht], w3 = sw[g][jj + 3][ht];
            uint4 v0 = ldcg128(h8 + (size_t)s0 * 64 + t);
            uint4 v1 = ldcg128(h8 + (size_t)s1 * 64 + t);
            uint4 v2 = ldcg128(h8 + (size_t)s2 * 64 + t);
            uint4 v3 = ldcg128(h8 + (size_t)s3 * 64 + t);
            den += (w0 + w1) + (w2 + w3);
            const __half2* p0 = (const __half2*)&v0;
            const __half2* p1 = (const __half2*)&v1;
            const __half2* p2 = (const __half2*)&v2;
            const __half2* p3 = (const __half2*)&v3;
            #pragma unroll
            for (int q = 0; q < 4; q++) {
                float2 f0 = __half22float2(p0[q]);
                float2 f1 = __half22float2(p1[q]);
                float2 f2 = __half22float2(p2[q]);
                float2 f3 = __half22float2(p3[q]);
                acc[q * 2 + 0] += (w0 * f0.x + w1 * f1.x) + (w2 * f2.x + w3 * f3.x);
                acc[q * 2 + 1] += (w0 * f0.y + w1 * f1.y) + (w2 * f2.y + w3 * f3.y);
            }
        }
        for (; jj < clen; jj++) {
            int s0 = ssrc[g][jj];
            float w0 = sw[g][jj][ht];
            uint4 v0 = ldcg128(h8 + (size_t)s0 * 64 + t);
            den += w0;
            const __half2* p0 = (const __half2*)&v0;
            #pragma unroll
            for (int q = 0; q < 4; q++) {
                float2 f0 = __half22float2(p0[q]);
                acc[q * 2 + 0] += w0 * f0.x;
                acc[q * 2 + 1] += w0 * f0.y;
            }
        }
        __syncthreads();   // protect sw/ssrc reuse next chunk
    }

    // bias + ELU + fused 512->2 projection
    int c = t * 8;
    float4 bv0 = *(const float4*)(b1 + c);
    float4 bv1 = *(const float4*)(b1 + c + 4);
    float bvs[8] = {bv0.x, bv0.y, bv0.z, bv0.w, bv1.x, bv1.y, bv1.z, bv1.w};
    float inv = 1.f / den;
    float p0 = 0.f, p1 = 0.f;
    #pragma unroll
    for (int q = 0; q < 8; q++) {
        float o = acc[q] * inv + bvs[q];
        o = (o > 0.f) ? o : (__expf(o) - 1.f);
        p0 += o * W2[(c + q) * 2];
        p1 += o * W2[(c + q) * 2 + 1];
    }
    #pragma unroll
    for (int o = 16; o; o >>= 1) {
        p0 += __shfl_xor_sync(0xffffffffu, p0, o);
        p1 += __shfl_xor_sync(0xffffffffu, p1, o);
    }
    if ((t & 31) == 0) { red[g][t >> 5][0] = p0; red[g][t >> 5][1] = p1; }
    __syncthreads();
    if (t == 0) {
        float h20 = red[g][0][0] + red[g][1][0];
        float h21 = red[g][0][1] + red[g][1][1];
        g_h2[n * 2 + 0] = h20;
        g_h2[n * 2 + 1] = h21;
        g_as2[n] = h20 * asrc2[0] + h21 * asrc2[1];
        g_ad2[n] = h20 * adst2[0] + h21 * adst2[1];
    }
}

// ---------------- layer-2 softmax + aggregation (warp per node) -------------
__global__ void k_agg2(const float* __restrict__ b2, float* __restrict__ out) {
    int gw = (blockIdx.x * blockDim.x + threadIdx.x) >> 5;
    int lane = threadIdx.x & 31;
    if (gw >= N_NODES) return;
    int start = g_off[gw], end = g_off[gw + 1];
    float adn = g_ad2[gw];

    float den = 0.f, a0 = 0.f, a1 = 0.f;
    for (int j = start + lane; j < end; j += 32) {
        int src = g_csr_src[j];
        float e = g_as2[src] + adn;
        e = (e > 0.f) ? e : NEG_SLOPE * e;
        float w = __expf(e);
        den += w;
        a0 += w * g_h2[src * 2 + 0];
        a1 += w * g_h2[src * 2 + 1];
    }
    #pragma unroll
    for (int off = 16; off; off >>= 1) {
        den += __shfl_xor_sync(0xffffffffu, den, off);
        a0  += __shfl_xor_sync(0xffffffffu, a0, off);
        a1  += __shfl_xor_sync(0xffffffffu, a1, off);
    }
    if (lane == 0) {
        float inv = 1.f / den;
        out[gw * 2 + 0] = a0 * inv + b2[0];
        out[gw * 2 + 1] = a1 * inv + b2[1];
    }
}

// ---------------- launcher ---------------------------------------------------
extern "C" void kernel_launch(void* const* d_in, const int* in_sizes, int n_in,
                              void* d_out, int out_size) {
    const float* x      = (const float*)d_in[0];
    const int*   ei     = (const int*)  d_in[1];
    const float* W1     = (const float*)d_in[2];
    const float* a_src1 = (const float*)d_in[3];
    const float* a_dst1 = (const float*)d_in[4];
    const float* b1     = (const float*)d_in[5];
    const float* W2     = (const float*)d_in[6];
    const float* a_src2 = (const float*)d_in[7];
    const float* a_dst2 = (const float*)d_in[8];
    const float* b2     = (const float*)d_in[9];
    float* out = (float*)d_out;

    static int configured = 0;
    static cudaStream_t s1 = 0;
    static cudaEvent_t evF = 0, evJ = 0;
    static int overlap_ok = 0;
    if (!configured) {
        cudaFuncSetAttribute(k_gemm_mma,
                             cudaFuncAttributeMaxDynamicSharedMemorySize,
                             GEMM_SMEM);
        if (cudaStreamCreateWithFlags(&s1, cudaStreamNonBlocking) == cudaSuccess &&
            cudaEventCreateWithFlags(&evF, cudaEventDisableTiming) == cudaSuccess &&
            cudaEventCreateWithFlags(&evJ, cudaEventDisableTiming) == cudaSuccess)
            overlap_ok = 1;
        configured = 1;
    }

    int prep_grid = (PREP_NA + F1 * IN_CH + 255) / 256;
    dim3 gg((N_NODES + 127) / 128, 4);

    if (overlap_ok) {
        // fork: CSR (fused single kernel) on s1; prep+GEMM on default stream
        cudaEventRecord(evF, 0);
        cudaStreamWaitEvent(s1, evF, 0);

        k_csr<<<148, 1024, 0, s1>>>(ei);          // submission 1
        cudaEventRecord(evJ, s1);

        k_prep<<<prep_grid, 256>>>(x, W1);        // submission 2
        k_gemm_mma<<<gg, 256, GEMM_SMEM>>>(a_src1, a_dst1);  // submission 3

        cudaStreamWaitEvent(0, evJ, 0);           // join
    } else {
        k_prep<<<prep_grid, 256>>>(x, W1);
        k_csr<<<148, 1024>>>(ei);
        k_gemm_mma<<<gg, 256, GEMM_SMEM>>>(a_src1, a_dst1);
    }

    // layer-1 aggregation fused with layer-2 feature projection — submission 4
    k_agg1<<<N_NODES / 4, 256>>>(b1, W2, a_src2, a_dst2);

    // layer 2 aggregation -> output — submission 5
    k_agg2<<<(N_NODES + 7) / 8, 256>>>(b2, out);
}

// round 12
// speedup vs baseline: 1.0649x; 1.0649x over previous
#include <cuda_runtime.h>
#include <cuda_fp16.h>
#include <cstdint>

#define N_NODES 50000
#define N_EDGES 800000
#define ET (N_EDGES + N_NODES)   // edges + self loops = 850000
#define IN_CH 128
#define H1 8
#define C1 64
#define F1 (H1 * C1)             // 512
#define NEG_SLOPE 0.2f

// ---------------- scratch (static device globals; no allocation) ------------
__device__ __half g_h1h[N_NODES * F1];    // x @ W1 in fp16   (51.2 MB)
__device__ float g_as1[N_NODES * H1];
__device__ float g_ad1[N_NODES * H1];
__device__ float g_h2[N_NODES * 2];
__device__ float g_as2[N_NODES];
__device__ float g_ad2[N_NODES];
__device__ int   g_deg[N_NODES];
__device__ int   g_off[N_NODES + 1];
__device__ int   g_cur[N_NODES];
__device__ int   g_csr_src[ET];

__device__ __half g_ah[N_NODES * IN_CH];   // fp16(x)    [m][k]
__device__ __half g_bh[F1 * IN_CH];        // fp16(W1^T) [n][k]

// ---------------- PTX helpers ------------------------------------------------
__device__ __forceinline__ uint32_t smem_u32(const void* p) {
    uint32_t a;
    asm("{ .reg .u64 t; cvta.to.shared.u64 t, %1; cvt.u32.u64 %0, t; }"
        : "=r"(a) : "l"(p));
    return a;
}

__device__ __forceinline__ void ldm_x4(uint32_t* r, uint32_t addr) {
    asm volatile("ldmatrix.sync.aligned.m8n8.x4.shared.b16 {%0,%1,%2,%3}, [%4];"
                 : "=r"(r[0]), "=r"(r[1]), "=r"(r[2]), "=r"(r[3]) : "r"(addr));
}

__device__ __forceinline__ void mma_fp16(float* d, const uint32_t* a,
                                         const uint32_t* b) {
    asm volatile("mma.sync.aligned.m16n8k16.row.col.f32.f16.f16.f32 "
                 "{%0,%1,%2,%3}, {%4,%5,%6,%7}, {%8,%9}, {%0,%1,%2,%3};"
                 : "+f"(d[0]), "+f"(d[1]), "+f"(d[2]), "+f"(d[3])
                 : "r"(a[0]), "r"(a[1]), "r"(a[2]), "r"(a[3]),
                   "r"(b[0]), "r"(b[1]));
}

__device__ __forceinline__ void cp16(uint32_t dst, const void* src,
                                     uint32_t src_bytes) {
    asm volatile("cp.async.cg.shared.global [%0], [%1], 16, %2;"
                 :: "r"(dst), "l"(src), "r"(src_bytes));
}

__device__ __forceinline__ uint4 ldcg128(const uint4* p) {
    uint4 v;
    asm volatile("ld.global.cg.v4.u32 {%0,%1,%2,%3}, [%4];"
                 : "=r"(v.x), "=r"(v.y), "=r"(v.z), "=r"(v.w) : "l"(p));
    return v;
}

// ---------------- CSR build -------------------------------------------------
__global__ void k_count(const int* __restrict__ ei) {
    int e = blockIdx.x * blockDim.x + threadIdx.x;
    if (e < N_EDGES) atomicAdd(&g_deg[ei[N_EDGES + e]], 1);
}

__global__ void k_scan() {
    __shared__ int wsum[2][32];
    int t = threadIdx.x, lane = t & 31, w = t >> 5;
    int carry = 0;
    int p = 0;
    for (int base = 0; base < N_NODES; base += 4096, p ^= 1) {
        int i = base + t * 4;
        int c0 = 0, c1 = 0, c2 = 0, c3 = 0;
        if (i + 3 < N_NODES) {
            int4 v = *(int4*)&g_deg[i];
            *(int4*)&g_deg[i] = make_int4(0, 0, 0, 0);
            c0 = v.x + 1; c1 = v.y + 1; c2 = v.z + 1; c3 = v.w + 1;
        } else if (i < N_NODES) {
            int cc[4] = {0, 0, 0, 0};
            for (int q = 0; q < 4; q++)
                if (i + q < N_NODES) { cc[q] = g_deg[i + q] + 1; g_deg[i + q] = 0; }
            c0 = cc[0]; c1 = cc[1]; c2 = cc[2]; c3 = cc[3];
        }
        int tsum = c0 + c1 + c2 + c3;
        int s = tsum;
        #pragma unroll
        for (int o = 1; o < 32; o <<= 1) {
            int u = __shfl_up_sync(0xffffffffu, s, o);
            if (lane >= o) s += u;
        }
        if (lane == 31) wsum[p][w] = s;
        __syncthreads();
        if (w == 0) {
            int ws = wsum[p][lane];
            #pragma unroll
            for (int o = 1; o < 32; o <<= 1) {
                int u = __shfl_up_sync(0xffffffffu, ws, o);
                if (lane >= o) ws += u;
            }
            wsum[p][lane] = ws;
        }
        __syncthreads();
        int excl = carry + (w ? wsum[p][w - 1] : 0) + s - tsum;
        int o0 = excl, o1 = o0 + c0, o2 = o1 + c1, o3 = o2 + c2;
        if (i + 3 < N_NODES) {
            *(int4*)&g_off[i] = make_int4(o0, o1, o2, o3);
            *(int4*)&g_cur[i] = make_int4(o0, o1, o2, o3);
        } else {
            int oo[4] = {o0, o1, o2, o3};
            for (int q = 0; q < 4; q++)
                if (i + q < N_NODES) { g_off[i + q] = oo[q]; g_cur[i + q] = oo[q]; }
        }
        carry += wsum[p][31];
    }
    if (t == 0) g_off[N_NODES] = carry;   // = ET
}

__global__ void k_scatter(const int* __restrict__ ei) {
    int e = blockIdx.x * blockDim.x + threadIdx.x;
    if (e >= ET) return;
    int src, dst;
    if (e < N_EDGES) { src = ei[e]; dst = ei[N_EDGES + e]; }
    else             { src = dst = e - N_EDGES; }
    int pos = atomicAdd(&g_cur[dst], 1);
    g_csr_src[pos] = src;
}

// ---------------- operand prep ------------------------------------------------
__global__ void k_prep_a(const float* __restrict__ x) {
    int idx = blockIdx.x * blockDim.x + threadIdx.x;   // over 6.4M/4
    if (idx >= N_NODES * IN_CH / 4) return;
    float4 v = ((const float4*)x)[idx];
    __half2 h0 = __floats2half2_rn(v.x, v.y);
    __half2 h1 = __floats2half2_rn(v.z, v.w);
    ((uint2*)g_ah)[idx] = make_uint2(*(uint32_t*)&h0, *(uint32_t*)&h1);
}

__global__ void k_prep_b(const float* __restrict__ W) {
    int idx = blockIdx.x * blockDim.x + threadIdx.x;   // over 512*128
    if (idx >= F1 * IN_CH) return;
    int n = idx & (F1 - 1);
    int k = idx >> 9;
    g_bh[n * IN_CH + k] = __float2half_rn(W[k * F1 + n]);  // coalesced read
}

// ---------------- mma.sync GEMM: h1 = X @ W1  (+ fused attention scores) -----
#define AS_STRIDE 136             // halves per row (272B: 16B-aligned, 8-row conflict-free)
#define TILE_BYTES_SM (128 * AS_STRIDE * 2)      // 34816
#define GEMM_SMEM (2 * TILE_BYTES_SM + 1024)     // A + B + scs

__global__ void __launch_bounds__(256) k_gemm_mma(
        const float* __restrict__ asrc, const float* __restrict__ adst) {
    extern __shared__ char dyn[];
    uint32_t sA = smem_u32(dyn);
    uint32_t sB = sA + TILE_BYTES_SM;
    float* scs = (float*)(dyn + 2 * TILE_BYTES_SM);  // [0,128) a_src, [128,256) a_dst

    int tid = threadIdx.x;
    int lane = tid & 31, wid = tid >> 5;
    int wm = wid & 3, wn = wid >> 2;
    int bm = blockIdx.x * 128;
    int nb = blockIdx.y;                 // N block: cols [nb*128, nb*128+128)

    #pragma unroll
    for (int it = 0; it < 8; it++) {
        int idx = tid + it * 256;        // 0..2047
        int r = idx >> 4, c = idx & 15;
        int grow = bm + r;
        int ok = grow < N_NODES;
        const void* gp = g_ah + (size_t)(ok ? grow : 0) * IN_CH + c * 8;
        cp16(sA + (uint32_t)(r * AS_STRIDE + c * 8) * 2, gp, ok ? 16u : 0u);
    }
    #pragma unroll
    for (int it = 0; it < 8; it++) {
        int idx = tid + it * 256;
        int r = idx >> 4, c = idx & 15;
        const void* gp = g_bh + (size_t)(nb * 128 + r) * IN_CH + c * 8;
        cp16(sB + (uint32_t)(r * AS_STRIDE + c * 8) * 2, gp, 16u);
    }
    asm volatile("cp.async.commit_group;" ::: "memory");

    scs[tid] = (tid < 128) ? asrc[nb * 128 + tid] : adst[nb * 128 + tid - 128];

    float acc[2][8][4];
    #pragma unroll
    for (int i = 0; i < 2; i++)
        #pragma unroll
        for (int j = 0; j < 8; j++)
            #pragma unroll
            for (int q = 0; q < 4; q++) acc[i][j][q] = 0.f;

    uint32_t a_off0 = (uint32_t)((wm * 32 + (lane & 15)) * AS_STRIDE +
                                 (lane >> 4) * 8) * 2;
    uint32_t b_off0 = (uint32_t)(((lane >> 4) * 8 + (lane & 7)) * AS_STRIDE +
                                 ((lane >> 3) & 1) * 8) * 2;

    asm volatile("cp.async.wait_group 0;" ::: "memory");
    __syncthreads();

    #pragma unroll
    for (int ks = 0; ks < 8; ks++) {
        uint32_t af[2][4], bf[4][4];
        #pragma unroll
        for (int mt = 0; mt < 2; mt++)
            ldm_x4(af[mt], sA + a_off0 +
                   (uint32_t)(mt * 16 * AS_STRIDE + ks * 16) * 2);
        #pragma unroll
        for (int np = 0; np < 4; np++)
            ldm_x4(bf[np], sB + b_off0 +
                   (uint32_t)((wn * 64 + np * 16) * AS_STRIDE + ks * 16) * 2);
        #pragma unroll
        for (int mt = 0; mt < 2; mt++)
            #pragma unroll
            for (int np = 0; np < 4; np++) {
                mma_fp16(acc[mt][np * 2 + 0], af[mt], &bf[np][0]);
                mma_fp16(acc[mt][np * 2 + 1], af[mt], &bf[np][2]);
            }
    }

    // ---- epilogue: store h1 (fp16) + fused per-head attention scores --------
    int ql = lane & 3, qr = lane >> 2;
    int head = nb * 2 + wn;

    #pragma unroll
    for (int mt = 0; mt < 2; mt++) {
        int row0 = bm + wm * 32 + mt * 16 + qr;
        float sa0 = 0.f, sd0 = 0.f, sa8 = 0.f, sd8 = 0.f;
        #pragma unroll
        for (int nt = 0; nt < 8; nt++) {
            float d0 = acc[mt][nt][0], d1 = acc[mt][nt][1];
            float d2 = acc[mt][nt][2], d3 = acc[mt][nt][3];
            int cw = wn * 64 + nt * 8 + ql * 2;
            float v0 = scs[cw], v1 = scs[cw + 1];
            float u0 = scs[128 + cw], u1 = scs[128 + cw + 1];
            sa0 += d0 * v0 + d1 * v1;
            sd0 += d0 * u0 + d1 * u1;
            sa8 += d2 * v0 + d3 * v1;
            sd8 += d2 * u0 + d3 * u1;
            int col = nb * 128 + cw;
            if (row0 < N_NODES)
                *(__half2*)(g_h1h + (size_t)row0 * F1 + col) =
                    __floats2half2_rn(d0, d1);
            if (row0 + 8 < N_NODES)
                *(__half2*)(g_h1h + (size_t)(row0 + 8) * F1 + col) =
                    __floats2half2_rn(d2, d3);
        }
        #pragma unroll
        for (int o = 1; o <= 2; o <<= 1) {
            sa0 += __shfl_xor_sync(0xffffffffu, sa0, o);
            sd0 += __shfl_xor_sync(0xffffffffu, sd0, o);
            sa8 += __shfl_xor_sync(0xffffffffu, sa8, o);
            sd8 += __shfl_xor_sync(0xffffffffu, sd8, o);
        }
        if (ql == 0) {
            if (row0 < N_NODES) {
                g_as1[row0 * H1 + head] = sa0;
                g_ad1[row0 * H1 + head] = sd0;
            }
            if (row0 + 8 < N_NODES) {
                g_as1[(row0 + 8) * H1 + head] = sa8;
                g_ad1[(row0 + 8) * H1 + head] = sd8;
            }
        }
    }
}

// ---- layer-1 softmax + aggregation + bias + elu + FUSED layer-2 projection --
// 4 nodes per 256-thread block; 64-thread group per node, thread owns 8
// channels, ld.global.cg uint4 feature loads. __launch_bounds__(256,6) caps
// registers (~42) so 6 blocks/SM are resident (profiled occ was 59.6% at
// regs=48/5 blocks; L1tex 76.6% busy -> more warps feed the pipe).
__global__ void __launch_bounds__(256, 6) k_agg1(
        const float* __restrict__ b1, const float* __restrict__ W2,
        const float* __restrict__ asrc2, const float* __restrict__ adst2) {
    __shared__ int   ssrc[4][64];
    __shared__ float sw[4][64][8];
    __shared__ float sadn[4][8];
    __shared__ float red[4][2][2];
    __shared__ int   smaxd;

    int tid = threadIdx.x;
    int g = tid >> 6;          // node group 0..3
    int t = tid & 63;          // thread in group
    int n = blockIdx.x * 4 + g;          // 50000 = 12500*4, always valid
    int ht = t >> 3;           // head owned by this thread

    int start = g_off[n];
    int deg = g_off[n + 1] - start;
    if (t < 8) sadn[g][t] = g_ad1[n * H1 + t];
    if (tid == 0) smaxd = 0;
    __syncthreads();
    if (t == 0) atomicMax(&smaxd, deg);
    __syncthreads();
    int maxdeg = smaxd;

    float acc[8] = {0.f, 0.f, 0.f, 0.f, 0.f, 0.f, 0.f, 0.f};
    float den = 0.f;
    const uint4* h8 = (const uint4*)g_h1h;   // 8 halves per uint4, row=64 uint4

    for (int c0 = 0; c0 < maxdeg; c0 += 64) {
        int clen = deg - c0;
        clen = (clen > 64) ? 64 : clen;
        if (t < clen) {
            int src = g_csr_src[start + c0 + t];
            ssrc[g][t] = src;
            float4 s01 = *(const float4*)(g_as1 + src * H1);
            float4 s45 = *(const float4*)(g_as1 + src * H1 + 4);
            float es[8] = {s01.x, s01.y, s01.z, s01.w,
                           s45.x, s45.y, s45.z, s45.w};
            float wv[8];
            #pragma unroll
            for (int h = 0; h < 8; h++) {
                float e = es[h] + sadn[g][h];
                e = (e > 0.f) ? e : NEG_SLOPE * e;
                wv[h] = __expf(e);
            }
            *(float4*)&sw[g][t][0] = make_float4(wv[0], wv[1], wv[2], wv[3]);
            *(float4*)&sw[g][t][4] = make_float4(wv[4], wv[5], wv[6], wv[7]);
        }
        __syncthreads();

        int jj = 0;
        for (; jj + 2 <= clen; jj += 2) {
            int s0 = ssrc[g][jj], s1 = ssrc[g][jj + 1];
            float w0 = sw[g][jj][ht], w1 = sw[g][jj + 1][ht];
            uint4 v0 = ldcg128(h8 + (size_t)s0 * 64 + t);
            uint4 v1 = ldcg128(h8 + (size_t)s1 * 64 + t);
            den += w0 + w1;
            const __half2* p0 = (const __half2*)&v0;
            const __half2* p1 = (const __half2*)&v1;
            #pragma unroll
            for (int q = 0; q < 4; q++) {
                float2 f0 = __half22float2(p0[q]);
                float2 f1 = __half22float2(p1[q]);
                acc[q * 2 + 0] += w0 * f0.x + w1 * f1.x;
                acc[q * 2 + 1] += w0 * f0.y + w1 * f1.y;
            }
        }
        if (jj < clen) {
            int s0 = ssrc[g][jj];
            float w0 = sw[g][jj][ht];
            uint4 v0 = ldcg128(h8 + (size_t)s0 * 64 + t);
            den += w0;
            const __half2* p0 = (const __half2*)&v0;
            #pragma unroll
            for (int q = 0; q < 4; q++) {
                float2 f0 = __half22float2(p0[q]);
                acc[q * 2 + 0] += w0 * f0.x;
                acc[q * 2 + 1] += w0 * f0.y;
            }
        }
        __syncthreads();   // protect sw/ssrc reuse next chunk
    }

    // bias + ELU + fused 512->2 projection
    int c = t * 8;
    float4 bv0 = *(const float4*)(b1 + c);
    float4 bv1 = *(const float4*)(b1 + c + 4);
    float bvs[8] = {bv0.x, bv0.y, bv0.z, bv0.w, bv1.x, bv1.y, bv1.z, bv1.w};
    float inv = 1.f / den;
    float p0 = 0.f, p1 = 0.f;
    #pragma unroll
    for (int q = 0; q < 8; q++) {
        float o = acc[q] * inv + bvs[q];
        o = (o > 0.f) ? o : (__expf(o) - 1.f);
        p0 += o * W2[(c + q) * 2];
        p1 += o * W2[(c + q) * 2 + 1];
    }
    #pragma unroll
    for (int o = 16; o; o >>= 1) {
        p0 += __shfl_xor_sync(0xffffffffu, p0, o);
        p1 += __shfl_xor_sync(0xffffffffu, p1, o);
    }
    if ((t & 31) == 0) { red[g][t >> 5][0] = p0; red[g][t >> 5][1] = p1; }
    __syncthreads();
    if (t == 0) {
        float h20 = red[g][0][0] + red[g][1][0];
        float h21 = red[g][0][1] + red[g][1][1];
        g_h2[n * 2 + 0] = h20;
        g_h2[n * 2 + 1] = h21;
        g_as2[n] = h20 * asrc2[0] + h21 * asrc2[1];
        g_ad2[n] = h20 * adst2[0] + h21 * adst2[1];
    }
}

// ---------------- layer-2 softmax + aggregation (warp per node) -------------
__global__ void k_agg2(const float* __restrict__ b2, float* __restrict__ out) {
    int gw = (blockIdx.x * blockDim.x + threadIdx.x) >> 5;
    int lane = threadIdx.x & 31;
    if (gw >= N_NODES) return;
    int start = g_off[gw], end = g_off[gw + 1];
    float adn = g_ad2[gw];

    float den = 0.f, a0 = 0.f, a1 = 0.f;
    for (int j = start + lane; j < end; j += 32) {
        int src = g_csr_src[j];
        float e = g_as2[src] + adn;
        e = (e > 0.f) ? e : NEG_SLOPE * e;
        float w = __expf(e);
        den += w;
        a0 += w * g_h2[src * 2 + 0];
        a1 += w * g_h2[src * 2 + 1];
    }
    #pragma unroll
    for (int off = 16; off; off >>= 1) {
        den += __shfl_xor_sync(0xffffffffu, den, off);
        a0  += __shfl_xor_sync(0xffffffffu, a0, off);
        a1  += __shfl_xor_sync(0xffffffffu, a1, off);
    }
    if (lane == 0) {
        float inv = 1.f / den;
        out[gw * 2 + 0] = a0 * inv + b2[0];
        out[gw * 2 + 1] = a1 * inv + b2[1];
    }
}

// ---------------- launcher ---------------------------------------------------
extern "C" void kernel_launch(void* const* d_in, const int* in_sizes, int n_in,
                              void* d_out, int out_size) {
    const float* x      = (const float*)d_in[0];
    const int*   ei     = (const int*)  d_in[1];
    const float* W1     = (const float*)d_in[2];
    const float* a_src1 = (const float*)d_in[3];
    const float* a_dst1 = (const float*)d_in[4];
    const float* b1     = (const float*)d_in[5];
    const float* W2     = (const float*)d_in[6];
    const float* a_src2 = (const float*)d_in[7];
    const float* a_dst2 = (const float*)d_in[8];
    const float* b2     = (const float*)d_in[9];
    float* out = (float*)d_out;

    static int configured = 0;
    static cudaStream_t s1 = 0;
    static cudaEvent_t evF = 0, evJ = 0;
    static int overlap_ok = 0;
    if (!configured) {
        cudaFuncSetAttribute(k_gemm_mma,
                             cudaFuncAttributeMaxDynamicSharedMemorySize,
                             GEMM_SMEM);
        if (cudaStreamCreateWithFlags(&s1, cudaStreamNonBlocking) == cudaSuccess &&
            cudaEventCreateWithFlags(&evF, cudaEventDisableTiming) == cudaSuccess &&
            cudaEventCreateWithFlags(&evJ, cudaEventDisableTiming) == cudaSuccess)
            overlap_ok = 1;
        configured = 1;
    }

    if (overlap_ok) {
        // fork: CSR chain on s1, prep+GEMM chain on the default stream
        cudaEventRecord(evF, 0);
        cudaStreamWaitEvent(s1, evF, 0);

        k_count<<<(N_EDGES + 255) / 256, 256, 0, s1>>>(ei);
        k_scan<<<1, 1024, 0, s1>>>();
        k_scatter<<<(ET + 255) / 256, 256, 0, s1>>>(ei);
        cudaEventRecord(evJ, s1);

        k_prep_a<<<(N_NODES * IN_CH / 4 + 255) / 256, 256>>>(x);
        k_prep_b<<<(F1 * IN_CH + 255) / 256, 256>>>(W1);
        dim3 gg((N_NODES + 127) / 128, 4);
        k_gemm_mma<<<gg, 256, GEMM_SMEM>>>(a_src1, a_dst1);

        // join
        cudaStreamWaitEvent(0, evJ, 0);
    } else {
        k_prep_a<<<(N_NODES * IN_CH / 4 + 255) / 256, 256>>>(x);
        k_prep_b<<<(F1 * IN_CH + 255) / 256, 256>>>(W1);
        k_count<<<(N_EDGES + 255) / 256, 256>>>(ei);
        dim3 gg((N_NODES + 127) / 128, 4);
        k_gemm_mma<<<gg, 256, GEMM_SMEM>>>(a_src1, a_dst1);
        k_scan<<<1, 1024>>>();
        k_scatter<<<(ET + 255) / 256, 256>>>(ei);
    }

    // layer-1 aggregation fused with layer-2 feature projection
    k_agg1<<<N_NODES / 4, 256>>>(b1, W2, a_src2, a_dst2);

    // layer 2 aggregation -> output
    k_agg2<<<(N_NODES + 7) / 8, 256>>>(b2, out);
}